// round 9
// baseline (speedup 1.0000x reference)
#include <cuda_runtime.h>
#include <math.h>

#define BB 8
#define SS 1024
#define HH 8
#define NTOK 8192

// ---------------- device scratch ----------------
__device__ float g_q [NTOK*256];   // [token][h*32+k], l2-normalized
__device__ float g_k [NTOK*256];
__device__ float g_v [NTOK*512];   // TRANSPOSED: [b][h][c(64)][s(1024)]
__device__ float g_y [NTOK*512];
__device__ float g_t1[NTOK*512];
__device__ float g_z1[NTOK*512];
__device__ float g_t2[NTOK*512];

// ---------------- primitives ----------------
__device__ __forceinline__ void mma8(float* c, const unsigned* a, const unsigned* b) {
    asm volatile(
        "mma.sync.aligned.m16n8k8.row.col.f32.tf32.tf32.f32 "
        "{%0,%1,%2,%3},{%4,%5,%6,%7},{%8,%9},{%0,%1,%2,%3};"
        : "+f"(c[0]), "+f"(c[1]), "+f"(c[2]), "+f"(c[3])
        : "r"(a[0]), "r"(a[1]), "r"(a[2]), "r"(a[3]), "r"(b[0]), "r"(b[1]));
}
// x4 b16 ldmatrix on tf32 data: lane l addresses row (R + (l&15)), k-col (K + (l>>4)*4).
__device__ __forceinline__ void ldsm4(unsigned* r, unsigned addr) {
    asm volatile("ldmatrix.sync.aligned.m8n8.x4.shared.b16 {%0,%1,%2,%3}, [%4];"
        : "=r"(r[0]), "=r"(r[1]), "=r"(r[2]), "=r"(r[3]) : "r"(addr));
}
__device__ __forceinline__ void cpa16(unsigned dst, const void* src) {
    asm volatile("cp.async.cg.shared.global [%0], [%1], 16;\n" :: "r"(dst), "l"(src));
}
#define CP_COMMIT asm volatile("cp.async.commit_group;\n" ::: "memory")
#define CP_WAIT0  asm volatile("cp.async.wait_group 0;\n" ::: "memory")
#define CP_WAIT1  asm volatile("cp.async.wait_group 1;\n" ::: "memory")

// ---------------- GEMM: C[M,N] = A[M,K] * W[N,K]^T, 3-stage pipeline ----------------
#define GST 36
#define GSTG (128*GST)
#define GSTAGE (2*GSTG)
#define GEMM_SMEM_BYTES (3*GSTAGE*4)   /* 110592 */

template<bool QKV>
__global__ __launch_bounds__(256, 2) void gemm_k(
    const float* __restrict__ A, const float* __restrict__ W0,
    const float* __restrict__ W1, const float* __restrict__ W2,
    const float* __restrict__ bias,
    float* __restrict__ C0, float* __restrict__ C1, float* __restrict__ C2,
    int Ngen, int K, int act)
{
    extern __shared__ unsigned gsm[];   // [3 stages][A 128x36 | W 128x36]

    const int tid = threadIdx.x, warp = tid >> 5, lane = tid & 31;
    const int g = lane >> 2, c = lane & 3;
    const int lrow = lane & 15, lk4 = (lane >> 4) << 2;
    const int warpM = (warp >> 1) * 32, warpN = (warp & 1) * 64;
    const int m0 = blockIdx.y * 128, bx = blockIdx.x;

    const float* W; float* C; int Nout, col0; bool norm = false, vmode = false;
    if (QKV) {
        if (bx < 2)      { W = W0; C = C0; Nout = 256; col0 = bx * 128;       norm = true; }
        else if (bx < 4) { W = W1; C = C1; Nout = 256; col0 = (bx - 2) * 128; norm = true; }
        else             { W = W2; C = C2; Nout = 512; col0 = (bx - 4) * 128; vmode = true; }
    } else { W = W0; C = C0; Nout = Ngen; col0 = bx * 128; }

    const unsigned sB = (unsigned)__cvta_generic_to_shared(gsm);

    auto pre = [&](int kc, int st) {
        const int k0 = kc * 32;
        const unsigned base = sB + (unsigned)(st * GSTAGE) * 4;
#pragma unroll
        for (int i = 0; i < 4; i++) {
            int slot = tid + i * 256;
            int row = slot >> 3, ch = (slot & 7) * 4;
            cpa16(base + (unsigned)(row * GST + ch) * 4,
                  A + (size_t)(m0 + row) * K + k0 + ch);
            cpa16(base + (unsigned)(GSTG + row * GST + ch) * 4,
                  W + (size_t)(col0 + row) * K + k0 + ch);
        }
    };

    float acc[2][8][4];
#pragma unroll
    for (int mi = 0; mi < 2; mi++)
#pragma unroll
        for (int ni = 0; ni < 8; ni++)
#pragma unroll
            for (int j = 0; j < 4; j++) acc[mi][ni][j] = 0.f;

    const int NC = K / 32;
    pre(0, 0); CP_COMMIT;
    pre(1, 1); CP_COMMIT;
    int st = 0;
    for (int kc = 0; kc < NC; kc++) {
        CP_WAIT1;
        __syncthreads();
        if (kc + 2 < NC) pre(kc + 2, (st + 2) % 3);
        CP_COMMIT;
        const unsigned abase = sB + (unsigned)(st * GSTAGE) * 4;
        const unsigned wbase = abase + (unsigned)GSTG * 4;
#pragma unroll
        for (int kk = 0; kk < 32; kk += 8) {
            unsigned af[2][4];
#pragma unroll
            for (int mi = 0; mi < 2; mi++)
                ldsm4(af[mi], abase + (unsigned)((warpM + mi * 16 + lrow) * GST + kk + lk4) * 4);
            unsigned bq[4][4];
#pragma unroll
            for (int p = 0; p < 4; p++)
                ldsm4(bq[p], wbase + (unsigned)((warpN + p * 16 + lrow) * GST + kk + lk4) * 4);
#pragma unroll
            for (int ni = 0; ni < 8; ni++) {
                unsigned bf[2] = { bq[ni >> 1][ni & 1], bq[ni >> 1][2 + (ni & 1)] };
#pragma unroll
                for (int mi = 0; mi < 2; mi++) mma8(acc[mi][ni], af[mi], bf);
            }
        }
        st = (st + 1) % 3;
    }

#pragma unroll
    for (int mi = 0; mi < 2; mi++) {
        float r0A = 1.f, r0B = 1.f, r1A = 1.f, r1B = 1.f;
        if (QKV && norm) {
            float a0 = 0.f, a1 = 0.f, b0 = 0.f, b1 = 0.f;
#pragma unroll
            for (int ni = 0; ni < 4; ni++) {
                a0 += acc[mi][ni][0]*acc[mi][ni][0] + acc[mi][ni][1]*acc[mi][ni][1];
                a1 += acc[mi][ni][2]*acc[mi][ni][2] + acc[mi][ni][3]*acc[mi][ni][3];
            }
#pragma unroll
            for (int ni = 4; ni < 8; ni++) {
                b0 += acc[mi][ni][0]*acc[mi][ni][0] + acc[mi][ni][1]*acc[mi][ni][1];
                b1 += acc[mi][ni][2]*acc[mi][ni][2] + acc[mi][ni][3]*acc[mi][ni][3];
            }
            a0 += __shfl_xor_sync(0xffffffffu, a0, 1); a0 += __shfl_xor_sync(0xffffffffu, a0, 2);
            a1 += __shfl_xor_sync(0xffffffffu, a1, 1); a1 += __shfl_xor_sync(0xffffffffu, a1, 2);
            b0 += __shfl_xor_sync(0xffffffffu, b0, 1); b0 += __shfl_xor_sync(0xffffffffu, b0, 2);
            b1 += __shfl_xor_sync(0xffffffffu, b1, 1); b1 += __shfl_xor_sync(0xffffffffu, b1, 2);
            r0A = 1.f / fmaxf(sqrtf(a0), 1e-12f);
            r1A = 1.f / fmaxf(sqrtf(a1), 1e-12f);
            r0B = 1.f / fmaxf(sqrtf(b0), 1e-12f);
            r1B = 1.f / fmaxf(sqrtf(b1), 1e-12f);
        }
        const int row0 = m0 + warpM + mi * 16 + g;
#pragma unroll
        for (int ni = 0; ni < 8; ni++) {
            const int col = col0 + warpN + ni * 8 + 2 * c;
            float o0 = acc[mi][ni][0], o1 = acc[mi][ni][1];
            float o2 = acc[mi][ni][2], o3 = acc[mi][ni][3];
            if (QKV) {
                if (norm) {
                    float ra = (ni < 4) ? r0A : r0B;
                    float rb = (ni < 4) ? r1A : r1B;
                    o0 *= ra; o1 *= ra; o2 *= rb; o3 *= rb;
                }
            } else {
                float bx_ = bias[col], by_ = bias[col + 1];
                o0 += bx_; o1 += by_; o2 += bx_; o3 += by_;
                if (act) {
                    o0 = o0 > 0.f ? o0 : 0.01f * o0;
                    o1 = o1 > 0.f ? o1 : 0.01f * o1;
                    o2 = o2 > 0.f ? o2 : 0.01f * o2;
                    o3 = o3 > 0.f ? o3 : 0.01f * o3;
                }
            }
            if (QKV && vmode) {
                int h = col >> 6, cc = col & 63;
                int bidx = row0 >> 10, s = row0 & 1023;
                float* vt = C + ((size_t)(bidx * 8 + h) * 64 + cc) * 1024 + s;
                vt[0]        = o0;
                vt[1024]     = o1;
                vt[8]        = o2;
                vt[1024 + 8] = o3;
            } else {
                *(float2*)&C[(size_t)row0 * Nout + col]       = make_float2(o0, o1);
                *(float2*)&C[(size_t)(row0 + 8) * Nout + col] = make_float2(o2, o3);
            }
        }
    }
}

// ---- fused attention: CTA 128(q) x 64(t), warp tile m16 x n64, z in registers ----
#define KST 36
#define VST 68
#define QWORDS (128*KST)
#define KTILE (64*KST)
#define VTILE (64*VST)
#define STG_WORDS (KTILE + VTILE)
#define ATT_WORDS (QWORDS + 3*STG_WORDS)
#define ATT_SMEM_BYTES (ATT_WORDS*4)   /* 98304 */

__global__ __launch_bounds__(256, 2) void attn6(
    const float* __restrict__ qn, const float* __restrict__ kn,
    const float* __restrict__ vt, const float* __restrict__ dist,
    const float* __restrict__ omega, float* __restrict__ yout)
{
    extern __shared__ unsigned sm[];

    const int h = blockIdx.x, b = blockIdx.y;
    const int qi = (int)(gridDim.z - 1 - blockIdx.z);   // heavy CTAs first
    const int q0 = qi * 128;
    const int tid = threadIdx.x, warp = tid >> 5, lane = tid & 31;
    const int g = lane >> 2, c = lane & 3;
    const bool codd = (c & 1) != 0;
    const int lrow = lane & 15, lk4 = (lane >> 4) << 2;
    const int warpM = warp * 16;
    const float om = omega[h];
    const int src1 = (lane & 28) | ((lane >> 1) & 1);   // lane 4g + (c>>1)

    const unsigned sq = (unsigned)__cvta_generic_to_shared(sm);
    const unsigned sstg = sq + (unsigned)QWORDS * 4;

    const float* vbase = vt + (size_t)(b * 8 + h) * 64 * 1024;

    auto ldK = [&](int st, int t0) {
        const unsigned kb = sstg + (unsigned)(st * STG_WORDS) * 4;
#pragma unroll
        for (int i = 0; i < 2; i++) {
            int slot = tid + i * 256, row = slot >> 3, ch = (slot & 7) * 4;
            cpa16(kb + (unsigned)(row * KST + ch) * 4,
                  kn + (size_t)(b * SS + t0 + row) * 256 + h * 32 + ch);
        }
    };
    auto ldV = [&](int st, int t0) {
        const unsigned vb = sstg + (unsigned)(st * STG_WORDS + KTILE) * 4;
#pragma unroll
        for (int i = 0; i < 4; i++) {
            int slot = tid + i * 256, row = slot >> 4, ch = (slot & 15) * 4;
            cpa16(vb + (unsigned)(row * VST + ch) * 4,
                  vbase + (size_t)row * 1024 + t0 + ch);
        }
    };
    // Q tile (128 x 32)
#pragma unroll
    for (int i = 0; i < 4; i++) {
        int slot = tid + i * 256, row = slot >> 3, ch = (slot & 7) * 4;
        cpa16(sq + (unsigned)(row * KST + ch) * 4,
              qn + (size_t)(b * SS + q0 + row) * 256 + h * 32 + ch);
    }
    ldK(0, 0); ldV(0, 0); CP_COMMIT;
    ldK(1, 64); ldV(1, 64); CP_COMMIT;   // nkt >= 2 always

    float oacc[8][4];
#pragma unroll
    for (int ni = 0; ni < 8; ni++)
#pragma unroll
        for (int j = 0; j < 4; j++) oacc[ni][j] = 0.f;
    float rs0 = 0.f, rs1 = 0.f;

    const int nkt = 2 * qi + 2;
    const int qrow0 = q0 + warpM + g, qrow1 = qrow0 + 8;

    for (int kt = 0; kt < nkt; kt++) {
        const int t0 = kt * 64;
        CP_WAIT1;
        __syncthreads();
        if (kt + 2 < nkt) { ldK((kt + 2) % 3, t0 + 128); ldV((kt + 2) % 3, t0 + 128); }
        CP_COMMIT;

        const unsigned skb = sstg + (unsigned)((kt % 3) * STG_WORDS) * 4;
        const unsigned svb = skb + (unsigned)KTILE * 4;

        // ---- S = Q K^T : warp computes S[16, 64] ----
        float sfr[8][4];
#pragma unroll
        for (int ni = 0; ni < 8; ni++)
#pragma unroll
            for (int j = 0; j < 4; j++) sfr[ni][j] = 0.f;
#pragma unroll
        for (int kk = 0; kk < 4; kk++) {
            unsigned af[4];
            ldsm4(af, sq + (unsigned)((warpM + lrow) * KST + kk * 8 + lk4) * 4);
            unsigned bq[4][4];
#pragma unroll
            for (int p = 0; p < 4; p++)
                ldsm4(bq[p], skb + (unsigned)((p * 16 + lrow) * KST + kk * 8 + lk4) * 4);
#pragma unroll
            for (int ni = 0; ni < 8; ni++) {
                unsigned bf[2] = { bq[ni >> 1][ni & 1], bq[ni >> 1][2 + (ni & 1)] };
                mma8(sfr[ni], af, bf);
            }
        }

        // ---- fused epilogue + AV, per k8-tile j; z stays in registers ----
        const bool needmask = (kt >= 2 * qi);
        const float* dr0 = dist + (size_t)(b * SS + qrow0) * SS + t0;
        const float* dr1 = dr0 + 8 * SS;
#pragma unroll
        for (int j = 0; j < 8; j++) {
            const int tcl = j * 8 + 2 * c;
            float2 d0 = __ldg((const float2*)(dr0 + tcl));
            float2 d1 = __ldg((const float2*)(dr1 + tcl));
            float z0 = __expf(sfr[j][0] + __expf(-om * d0.x) - 1.f);
            float z1 = __expf(sfr[j][1] + __expf(-om * d0.y) - 1.f);
            float z2 = __expf(sfr[j][2] + __expf(-om * d1.x) - 1.f);
            float z3 = __expf(sfr[j][3] + __expf(-om * d1.y) - 1.f);
            if (needmask) {
                const int tc0 = t0 + tcl;
                if (tc0     > qrow0) z0 = 0.f;
                if (tc0 + 1 > qrow0) z1 = 0.f;
                if (tc0     > qrow1) z2 = 0.f;
                if (tc0 + 1 > qrow1) z3 = 0.f;
            }
            rs0 += z0 + z1;
            rs1 += z2 + z3;
            // permute S-frag (cols {2c,2c+1}) -> A-frag (cols {c, c+4})
            float v0 = __shfl_sync(0xffffffffu, z0, src1);
            float v1 = __shfl_sync(0xffffffffu, z1, src1);
            float v2 = __shfl_sync(0xffffffffu, z2, src1);
            float v3 = __shfl_sync(0xffffffffu, z3, src1);
            float w0 = __shfl_sync(0xffffffffu, z0, src1 + 2);
            float w1 = __shfl_sync(0xffffffffu, z1, src1 + 2);
            float w2 = __shfl_sync(0xffffffffu, z2, src1 + 2);
            float w3 = __shfl_sync(0xffffffffu, z3, src1 + 2);
            unsigned za[4];
            za[0] = __float_as_uint(codd ? v1 : v0);
            za[1] = __float_as_uint(codd ? v3 : v2);
            za[2] = __float_as_uint(codd ? w1 : w0);
            za[3] = __float_as_uint(codd ? w3 : w2);
            // V^T B-frags at kk = j
            unsigned bq[4][4];
#pragma unroll
            for (int p = 0; p < 4; p++)
                ldsm4(bq[p], svb + (unsigned)((p * 16 + lrow) * VST + j * 8 + lk4) * 4);
#pragma unroll
            for (int ni = 0; ni < 8; ni++) {
                unsigned bf[2] = { bq[ni >> 1][ni & 1], bq[ni >> 1][2 + (ni & 1)] };
                mma8(oacc[ni], za, bf);
            }
        }
    }

    // ---- in-warp row sums; normalize; store concat layout ----
    rs0 += __shfl_xor_sync(0xffffffffu, rs0, 1);
    rs0 += __shfl_xor_sync(0xffffffffu, rs0, 2);
    rs1 += __shfl_xor_sync(0xffffffffu, rs1, 1);
    rs1 += __shfl_xor_sync(0xffffffffu, rs1, 2);
    const float inv0 = 1.f / (rs0 + 1.f);
    const float inv1 = 1.f / (rs1 + 1.f);
#pragma unroll
    for (int ni = 0; ni < 8; ni++) {
        const int col = h * 64 + ni * 8 + 2 * c;
        *(float2*)(yout + (size_t)(b * SS + qrow0) * 512 + col) =
            make_float2(oacc[ni][0] * inv0, oacc[ni][1] * inv0);
        *(float2*)(yout + (size_t)(b * SS + qrow1) * 512 + col) =
            make_float2(oacc[ni][2] * inv1, oacc[ni][3] * inv1);
    }
}

// ---------------- residual add + LayerNorm over 512 ----------------
__global__ __launch_bounds__(128) void add_ln_kernel(
    const float* __restrict__ A, const float* __restrict__ Bs,
    const float* __restrict__ w, const float* __restrict__ bias,
    float* __restrict__ out)
{
    const int row = blockIdx.x;
    const int t = threadIdx.x;
    __shared__ float red[8];

    float4 a4 = *(const float4*)(A  + (size_t)row * 512 + t * 4);
    float4 b4 = *(const float4*)(Bs + (size_t)row * 512 + t * 4);
    float v0 = a4.x + b4.x, v1 = a4.y + b4.y, v2 = a4.z + b4.z, v3 = a4.w + b4.w;

    float s = v0 + v1 + v2 + v3;
#pragma unroll
    for (int o = 16; o > 0; o >>= 1) s += __shfl_xor_sync(0xffffffffu, s, o);
    int wid = t >> 5, lane = t & 31;
    if (!lane) red[wid] = s;
    __syncthreads();
    float mean = (red[0] + red[1] + red[2] + red[3]) * (1.f / 512.f);

    float d0 = v0 - mean, d1 = v1 - mean, d2 = v2 - mean, d3 = v3 - mean;
    float sv = d0*d0 + d1*d1 + d2*d2 + d3*d3;
#pragma unroll
    for (int o = 16; o > 0; o >>= 1) sv += __shfl_xor_sync(0xffffffffu, sv, o);
    if (!lane) red[4 + wid] = sv;
    __syncthreads();
    float var = (red[4] + red[5] + red[6] + red[7]) * (1.f / 512.f);
    float rstd = rsqrtf(var + 1e-5f);

    float4 w4  = *(const float4*)(w    + t * 4);
    float4 bb4 = *(const float4*)(bias + t * 4);
    float4 o4;
    o4.x = d0 * rstd * w4.x + bb4.x;
    o4.y = d1 * rstd * w4.y + bb4.y;
    o4.z = d2 * rstd * w4.z + bb4.z;
    o4.w = d3 * rstd * w4.w + bb4.w;
    *(float4*)(out + (size_t)row * 512 + t * 4) = o4;
}

// ---------------- launch ----------------
extern "C" void kernel_launch(void* const* d_in, const int* in_sizes, int n_in,
                              void* d_out, int out_size)
{
    const float* x     = (const float*)d_in[0];
    const float* dist  = (const float*)d_in[2];
    const float* Wq    = (const float*)d_in[3];
    const float* Wk    = (const float*)d_in[4];
    const float* Wv    = (const float*)d_in[5];
    const float* omega = (const float*)d_in[6];
    const float* Wo    = (const float*)d_in[7];
    const float* bo    = (const float*)d_in[8];
    const float* Wf    = (const float*)d_in[9];
    const float* bf    = (const float*)d_in[10];
    const float* l1w   = (const float*)d_in[11];
    const float* l1b   = (const float*)d_in[12];
    const float* l2w   = (const float*)d_in[13];
    const float* l2b   = (const float*)d_in[14];
    float* out = (float*)d_out;

    float *gq, *gk, *gv, *gy, *gt1, *gz1, *gt2;
    cudaGetSymbolAddress((void**)&gq,  g_q);
    cudaGetSymbolAddress((void**)&gk,  g_k);
    cudaGetSymbolAddress((void**)&gv,  g_v);
    cudaGetSymbolAddress((void**)&gy,  g_y);
    cudaGetSymbolAddress((void**)&gt1, g_t1);
    cudaGetSymbolAddress((void**)&gz1, g_z1);
    cudaGetSymbolAddress((void**)&gt2, g_t2);

    cudaFuncSetAttribute(gemm_k<true>,  cudaFuncAttributeMaxDynamicSharedMemorySize, GEMM_SMEM_BYTES);
    cudaFuncSetAttribute(gemm_k<false>, cudaFuncAttributeMaxDynamicSharedMemorySize, GEMM_SMEM_BYTES);
    cudaFuncSetAttribute(attn6, cudaFuncAttributeMaxDynamicSharedMemorySize, ATT_SMEM_BYTES);

    // fused QKV projections + per-head l2norm; V written transposed
    gemm_k<true><<<dim3(8, 64), 256, GEMM_SMEM_BYTES>>>(x, Wq, Wk, Wv, nullptr,
                                                        gq, gk, gv, 0, 512, 0);

    // fused attention (z-in-registers, 3-stage pipeline, heavy CTAs first)
    attn6<<<dim3(HH, BB, SS / 128), 256, ATT_SMEM_BYTES>>>(gq, gk, gv, dist, omega, gy);

    // output projection + LN1
    gemm_k<false><<<dim3(4, 64), 256, GEMM_SMEM_BYTES>>>(gy, Wo, nullptr, nullptr, bo,
                                                         gt1, nullptr, nullptr, 512, 512, 0);
    add_ln_kernel<<<NTOK, 128>>>(x, gt1, l1w, l1b, gz1);

    // FFN + leaky relu + LN2
    gemm_k<false><<<dim3(4, 64), 256, GEMM_SMEM_BYTES>>>(gz1, Wf, nullptr, nullptr, bf,
                                                         gt2, nullptr, nullptr, 512, 512, 1);
    add_ln_kernel<<<NTOK, 128>>>(gz1, gt2, l2w, l2b, out);
}